// round 1
// baseline (speedup 1.0000x reference)
#include <cuda_runtime.h>

#define BATCH 4
#define SEQ   4096
#define CH    1024
#define NH    16
#define HD    64
#define BS    64
#define NB    (SEQ / BS)          // 64
#define MROWS (BATCH * SEQ)       // 16384

// ---------------- scratch (device globals: allocation-free) ----------------
__device__ float g_Q[(size_t)MROWS * CH];
__device__ float g_K[(size_t)MROWS * CH];
__device__ float g_V[(size_t)MROWS * CH];
__device__ float g_O[(size_t)MROWS * CH];

// ---------------- GEMM: Out[M,N] = A[M,K] @ W[N,K]^T + bias[N] -------------
// BM=BN=128, BK=16, 256 threads, 8x8 register tile per thread.
__global__ __launch_bounds__(256) void gemm_nt_bias(
    const float* __restrict__ A, const float* __restrict__ W,
    const float* __restrict__ bias, float* __restrict__ Out,
    int M, int N, int K)
{
    __shared__ float As[16][132];
    __shared__ float Bs[16][132];

    const int tid  = threadIdx.x;
    const int bm   = blockIdx.y * 128;
    const int bn   = blockIdx.x * 128;
    const int lrow = tid >> 2;           // 0..63
    const int lk4  = (tid & 3) << 2;     // 0,4,8,12
    const int mr   = (tid >> 4) << 3;    // 0..120 step 8
    const int nr   = (tid & 15) << 3;    // 0..120 step 8

    float acc[8][8];
#pragma unroll
    for (int i = 0; i < 8; i++)
#pragma unroll
        for (int j = 0; j < 8; j++) acc[i][j] = 0.0f;

    const float* Arow0 = A + (size_t)(bm + lrow)      * K;
    const float* Arow1 = A + (size_t)(bm + lrow + 64) * K;
    const float* Brow0 = W + (size_t)(bn + lrow)      * K;
    const float* Brow1 = W + (size_t)(bn + lrow + 64) * K;

    for (int k0 = 0; k0 < K; k0 += 16) {
        float4 a0 = *(const float4*)(Arow0 + k0 + lk4);
        float4 a1 = *(const float4*)(Arow1 + k0 + lk4);
        float4 b0 = *(const float4*)(Brow0 + k0 + lk4);
        float4 b1 = *(const float4*)(Brow1 + k0 + lk4);
        __syncthreads();
        As[lk4 + 0][lrow]      = a0.x; As[lk4 + 1][lrow]      = a0.y;
        As[lk4 + 2][lrow]      = a0.z; As[lk4 + 3][lrow]      = a0.w;
        As[lk4 + 0][lrow + 64] = a1.x; As[lk4 + 1][lrow + 64] = a1.y;
        As[lk4 + 2][lrow + 64] = a1.z; As[lk4 + 3][lrow + 64] = a1.w;
        Bs[lk4 + 0][lrow]      = b0.x; Bs[lk4 + 1][lrow]      = b0.y;
        Bs[lk4 + 2][lrow]      = b0.z; Bs[lk4 + 3][lrow]      = b0.w;
        Bs[lk4 + 0][lrow + 64] = b1.x; Bs[lk4 + 1][lrow + 64] = b1.y;
        Bs[lk4 + 2][lrow + 64] = b1.z; Bs[lk4 + 3][lrow + 64] = b1.w;
        __syncthreads();

#pragma unroll
        for (int kk = 0; kk < 16; kk++) {
            float a[8], b[8];
            *(float4*)(a)     = *(const float4*)&As[kk][mr];
            *(float4*)(a + 4) = *(const float4*)&As[kk][mr + 4];
            *(float4*)(b)     = *(const float4*)&Bs[kk][nr];
            *(float4*)(b + 4) = *(const float4*)&Bs[kk][nr + 4];
#pragma unroll
            for (int i = 0; i < 8; i++)
#pragma unroll
                for (int j = 0; j < 8; j++)
                    acc[i][j] += a[i] * b[j];
        }
    }

#pragma unroll
    for (int i = 0; i < 8; i++) {
        float* orow = Out + (size_t)(bm + mr + i) * N + bn + nr;
        float4 w0, w1;
        w0.x = acc[i][0] + bias[bn + nr + 0];
        w0.y = acc[i][1] + bias[bn + nr + 1];
        w0.z = acc[i][2] + bias[bn + nr + 2];
        w0.w = acc[i][3] + bias[bn + nr + 3];
        w1.x = acc[i][4] + bias[bn + nr + 4];
        w1.y = acc[i][5] + bias[bn + nr + 5];
        w1.z = acc[i][6] + bias[bn + nr + 6];
        w1.w = acc[i][7] + bias[bn + nr + 7];
        *(float4*)(orow)     = w0;
        *(float4*)(orow + 4) = w1;
    }
}

// ---------------- attention: one CTA per (block n, head h, batch b) --------
// smem layout (floats):
//   qT  [64][68]   q transposed: qT[dd][i]
//   kv  region: first used as kT[dd][j] ([64][196]) then as vs[j][dd] ([192][68])
//   Ss  [64][196]  scores / probabilities
#define QT_STRIDE 68
#define KT_STRIDE 196
#define SS_STRIDE 196
#define VS_STRIDE 68
#define QT_OFF 0
#define KV_OFF (64 * QT_STRIDE)                 // 4352
#define KV_FLOATS 13056                          // max(64*196, 192*68)
#define SS_OFF (KV_OFF + KV_FLOATS)              // 17408
#define SMEM_FLOATS (SS_OFF + 64 * SS_STRIDE)    // 29952
#define SMEM_BYTES (SMEM_FLOATS * 4)             // 119808

__global__ __launch_bounds__(256) void attn_kernel(
    const float* __restrict__ Q, const float* __restrict__ K,
    const float* __restrict__ V, float* __restrict__ O)
{
    extern __shared__ float sm[];
    float* qT = sm + QT_OFF;
    float* kT = sm + KV_OFF;
    float* vs = sm + KV_OFF;
    float* Ss = sm + SS_OFF;

    const int tid = threadIdx.x;
    const int n = blockIdx.x;
    const int h = blockIdx.y;
    const int b = blockIdx.z;
    const size_t base = (size_t)b * SEQ * CH + (size_t)h * HD;

    // load q (transposed into qT[dd][i])
#pragma unroll
    for (int p = 0; p < 4; p++) {
        int idx = tid + p * 256;         // 0..1023
        int i   = idx >> 4;              // 0..63
        int dd0 = (idx & 15) << 2;       // 0..60
        float4 v4 = *(const float4*)(Q + base + (size_t)(n * BS + i) * CH + dd0);
        qT[(dd0 + 0) * QT_STRIDE + i] = v4.x;
        qT[(dd0 + 1) * QT_STRIDE + i] = v4.y;
        qT[(dd0 + 2) * QT_STRIDE + i] = v4.z;
        qT[(dd0 + 3) * QT_STRIDE + i] = v4.w;
    }
    // load k window (transposed into kT[dd][j]); j in [0,192), kpos=(n-1)*64+j
#pragma unroll
    for (int p = 0; p < 12; p++) {
        int idx = tid + p * 256;         // 0..3071
        int j   = idx >> 4;              // 0..191
        int dd0 = (idx & 15) << 2;
        int kpos = (n - 1) * BS + j;
        float4 v4 = make_float4(0.f, 0.f, 0.f, 0.f);
        if (kpos >= 0 && kpos < SEQ)
            v4 = *(const float4*)(K + base + (size_t)kpos * CH + dd0);
        kT[(dd0 + 0) * KT_STRIDE + j] = v4.x;
        kT[(dd0 + 1) * KT_STRIDE + j] = v4.y;
        kT[(dd0 + 2) * KT_STRIDE + j] = v4.z;
        kT[(dd0 + 3) * KT_STRIDE + j] = v4.w;
    }
    __syncthreads();

    // S[i][j] = scale * sum_dd q[i][dd] k[j][dd]; thread tile 4 rows x 12 cols
    const int i0 = (tid >> 4) << 2;      // 0..60
    const int j0 = (tid & 15) * 12;      // 0..180
    float acc[4][12];
#pragma unroll
    for (int ii = 0; ii < 4; ii++)
#pragma unroll
        for (int jj = 0; jj < 12; jj++) acc[ii][jj] = 0.0f;

#pragma unroll 4
    for (int dd = 0; dd < 64; dd++) {
        float4 a4 = *(const float4*)&qT[dd * QT_STRIDE + i0];
        float4 b0 = *(const float4*)&kT[dd * KT_STRIDE + j0];
        float4 b1 = *(const float4*)&kT[dd * KT_STRIDE + j0 + 4];
        float4 b2 = *(const float4*)&kT[dd * KT_STRIDE + j0 + 8];
        float a[4] = {a4.x, a4.y, a4.z, a4.w};
        float bb[12] = {b0.x, b0.y, b0.z, b0.w, b1.x, b1.y, b1.z, b1.w,
                        b2.x, b2.y, b2.z, b2.w};
#pragma unroll
        for (int ii = 0; ii < 4; ii++)
#pragma unroll
            for (int jj = 0; jj < 12; jj++)
                acc[ii][jj] += a[ii] * bb[jj];
    }

    const float scale = 0.125f;          // 64^-0.5
#pragma unroll
    for (int ii = 0; ii < 4; ii++) {
        int i = i0 + ii;
#pragma unroll
        for (int jj = 0; jj < 12; jj++) {
            int j = j0 + jj;
            bool valid = (j <= i + BS) &&
                         (n > 0 || j >= BS) &&
                         (n < NB - 1 || j < 2 * BS);
            Ss[i * SS_STRIDE + j] = valid ? acc[ii][jj] * scale : -1e30f;
        }
    }
    __syncthreads();

    // softmax: 4 threads per row, strided columns; shuffle-reduce within quad
    {
        int r  = tid >> 2;
        int jc = tid & 3;
        float vals[48];
        float m = -1e30f;
#pragma unroll
        for (int t = 0; t < 48; t++) {
            vals[t] = Ss[r * SS_STRIDE + jc + 4 * t];
            m = fmaxf(m, vals[t]);
        }
        m = fmaxf(m, __shfl_xor_sync(0xffffffffu, m, 1));
        m = fmaxf(m, __shfl_xor_sync(0xffffffffu, m, 2));
        float s = 0.0f;
#pragma unroll
        for (int t = 0; t < 48; t++) {
            vals[t] = __expf(vals[t] - m);
            s += vals[t];
        }
        s += __shfl_xor_sync(0xffffffffu, s, 1);
        s += __shfl_xor_sync(0xffffffffu, s, 2);
        float inv = 1.0f / s;
#pragma unroll
        for (int t = 0; t < 48; t++)
            Ss[r * SS_STRIDE + jc + 4 * t] = vals[t] * inv;
    }

    // load v into the kv region (natural layout vs[j][dd]); kT no longer read
#pragma unroll
    for (int p = 0; p < 12; p++) {
        int idx = tid + p * 256;
        int j   = idx >> 4;
        int dd0 = (idx & 15) << 2;
        int kpos = (n - 1) * BS + j;
        float4 v4 = make_float4(0.f, 0.f, 0.f, 0.f);
        if (kpos >= 0 && kpos < SEQ)
            v4 = *(const float4*)(V + base + (size_t)kpos * CH + dd0);
        *(float4*)&vs[j * VS_STRIDE + dd0] = v4;
    }
    __syncthreads();

    // O[i][c] = sum_j P[i][j] * v[j][c]; thread tile 4x4
    const int c0 = (tid & 15) << 2;
    float o[4][4];
#pragma unroll
    for (int ii = 0; ii < 4; ii++)
#pragma unroll
        for (int cc = 0; cc < 4; cc++) o[ii][cc] = 0.0f;

#pragma unroll 4
    for (int j = 0; j < 192; j++) {
        float4 v4 = *(const float4*)&vs[j * VS_STRIDE + c0];
        float p0 = Ss[(i0 + 0) * SS_STRIDE + j];
        float p1 = Ss[(i0 + 1) * SS_STRIDE + j];
        float p2 = Ss[(i0 + 2) * SS_STRIDE + j];
        float p3 = Ss[(i0 + 3) * SS_STRIDE + j];
        o[0][0] += p0 * v4.x; o[0][1] += p0 * v4.y; o[0][2] += p0 * v4.z; o[0][3] += p0 * v4.w;
        o[1][0] += p1 * v4.x; o[1][1] += p1 * v4.y; o[1][2] += p1 * v4.z; o[1][3] += p1 * v4.w;
        o[2][0] += p2 * v4.x; o[2][1] += p2 * v4.y; o[2][2] += p2 * v4.z; o[2][3] += p2 * v4.w;
        o[3][0] += p3 * v4.x; o[3][1] += p3 * v4.y; o[3][2] += p3 * v4.z; o[3][3] += p3 * v4.w;
    }
#pragma unroll
    for (int ii = 0; ii < 4; ii++) {
        float4 w4 = make_float4(o[ii][0], o[ii][1], o[ii][2], o[ii][3]);
        *(float4*)(O + base + (size_t)(n * BS + i0 + ii) * CH + c0) = w4;
    }
}

// ---------------------------------------------------------------------------
extern "C" void kernel_launch(void* const* d_in, const int* in_sizes, int n_in,
                              void* d_out, int out_size)
{
    const float* x  = (const float*)d_in[0];
    const float* Wq = (const float*)d_in[1];
    const float* bq = (const float*)d_in[2];
    const float* Wk = (const float*)d_in[3];
    const float* bk = (const float*)d_in[4];
    const float* Wv = (const float*)d_in[5];
    const float* bv = (const float*)d_in[6];
    const float* Wo = (const float*)d_in[7];
    const float* bo = (const float*)d_in[8];
    float* out = (float*)d_out;

    float *qp, *kp, *vp, *op;
    cudaGetSymbolAddress((void**)&qp, g_Q);
    cudaGetSymbolAddress((void**)&kp, g_K);
    cudaGetSymbolAddress((void**)&vp, g_V);
    cudaGetSymbolAddress((void**)&op, g_O);

    cudaFuncSetAttribute(attn_kernel,
                         cudaFuncAttributeMaxDynamicSharedMemorySize, SMEM_BYTES);

    dim3 ggrid(CH / 128, MROWS / 128);
    gemm_nt_bias<<<ggrid, 256>>>(x,  Wq, bq, qp,  MROWS, CH, CH);
    gemm_nt_bias<<<ggrid, 256>>>(x,  Wk, bk, kp,  MROWS, CH, CH);
    gemm_nt_bias<<<ggrid, 256>>>(x,  Wv, bv, vp,  MROWS, CH, CH);
    attn_kernel<<<dim3(NB, NH, BATCH), 256, SMEM_BYTES>>>(qp, kp, vp, op);
    gemm_nt_bias<<<ggrid, 256>>>(op, Wo, bo, out, MROWS, CH, CH);
}

// round 3
// speedup vs baseline: 2.0673x; 2.0673x over previous
#include <cuda_runtime.h>
#include <cuda_fp16.h>
#include <cstdint>

#define BATCH 4
#define SEQ   4096
#define CH    1024
#define NH    16
#define HD    64
#define BS    64
#define NB    (SEQ / BS)          // 64
#define MROWS (BATCH * SEQ)       // 16384

// ---------------- scratch (device globals: allocation-free) ----------------
__device__ float g_Q[(size_t)MROWS * CH];
__device__ float g_K[(size_t)MROWS * CH];
__device__ float g_V[(size_t)MROWS * CH];
__device__ float g_O[(size_t)MROWS * CH];
__device__ __half g_Ahi[(size_t)MROWS * CH];
__device__ __half g_Alo[(size_t)MROWS * CH];
__device__ __half g_Phi[(size_t)MROWS * CH];
__device__ __half g_Plo[(size_t)MROWS * CH];
__device__ __half g_Whi[(size_t)4 * CH * CH];
__device__ __half g_Wlo[(size_t)4 * CH * CH];

// =================== helpers ===================
__device__ __forceinline__ uint32_t smem_u32(const void* p) {
    uint32_t a;
    asm("{ .reg .u64 t; cvta.to.shared.u64 t, %1; cvt.u32.u64 %0, t; }"
        : "=r"(a) : "l"(p));
    return a;
}
__device__ __forceinline__ void cp16(uint32_t dst, const void* src) {
    asm volatile("cp.async.cg.shared.global [%0], [%1], 16;" :: "r"(dst), "l"(src));
}
__device__ __forceinline__ void cp_commit() {
    asm volatile("cp.async.commit_group;" ::: "memory");
}
template <int N>
__device__ __forceinline__ void cp_wait() {
    asm volatile("cp.async.wait_group %0;" :: "n"(N) : "memory");
}
__device__ __forceinline__ void ldsm4(uint32_t& r0, uint32_t& r1, uint32_t& r2,
                                      uint32_t& r3, uint32_t addr) {
    asm volatile("ldmatrix.sync.aligned.m8n8.x4.shared.b16 {%0,%1,%2,%3}, [%4];"
                 : "=r"(r0), "=r"(r1), "=r"(r2), "=r"(r3) : "r"(addr));
}
__device__ __forceinline__ void mma16816(float* c, const uint32_t* a,
                                         uint32_t b0, uint32_t b1) {
    asm volatile(
        "mma.sync.aligned.m16n8k16.row.col.f32.f16.f16.f32 "
        "{%0,%1,%2,%3}, {%4,%5,%6,%7}, {%8,%9}, {%0,%1,%2,%3};"
        : "+f"(c[0]), "+f"(c[1]), "+f"(c[2]), "+f"(c[3])
        : "r"(a[0]), "r"(a[1]), "r"(a[2]), "r"(a[3]), "r"(b0), "r"(b1));
}

// =================== fp32 -> fp16 hi/lo splitter ===================
__global__ __launch_bounds__(256) void split_f16(
    const float* __restrict__ in, __half* __restrict__ hi,
    __half* __restrict__ lo, int n)
{
    int i = (blockIdx.x * 256 + threadIdx.x) * 4;
    if (i >= n) return;
    float4 v = *(const float4*)(in + i);
    __half h0 = __float2half(v.x);
    __half h1 = __float2half(v.y);
    __half h2 = __float2half(v.z);
    __half h3 = __float2half(v.w);
    __half l0 = __float2half(v.x - __half2float(h0));
    __half l1 = __float2half(v.y - __half2float(h1));
    __half l2 = __float2half(v.z - __half2float(h2));
    __half l3 = __float2half(v.w - __half2float(h3));
    __half2 hp0; hp0.x = h0; hp0.y = h1;
    __half2 hp1; hp1.x = h2; hp1.y = h3;
    __half2 lp0; lp0.x = l0; lp0.y = l1;
    __half2 lp1; lp1.x = l2; lp1.y = l3;
    *(__half2*)(hi + i)     = hp0;
    *(__half2*)(hi + i + 2) = hp1;
    *(__half2*)(lo + i)     = lp0;
    *(__half2*)(lo + i + 2) = lp1;
}

// =================== HMMA GEMM: Out[M,N] = A@W^T + bias (fp16x3) ============
// BM=BN=128, BK=32 halfs. 3-stage cp.async pipeline. 8 warps, warp tile 32x64.
// SMEM tile per operand: 128 rows x 32 halfs (64B/row), XOR swizzled.
#define BKH 32
#define NKC (CH / BKH)            // 32
#define HT_BYTES 8192             // 128 * 64B
#define HSTAGE (4 * HT_BYTES)     // Ahi, Alo, Bhi, Blo
#define HSTAGES 3
#define HGEMM_SMEM (HSTAGES * HSTAGE)   // 98304

__device__ __forceinline__ uint32_t sw_off(int row, int chunk) {
    return (uint32_t)(row * 64 + ((chunk ^ ((row >> 1) & 3)) << 4));
}

__global__ __launch_bounds__(256) void gemm_hmma(
    const __half* __restrict__ Ahi, const __half* __restrict__ Alo,
    const __half* __restrict__ Bhi, const __half* __restrict__ Blo,
    const float* __restrict__ bias, float* __restrict__ Out)
{
    extern __shared__ char dsm[];
    const uint32_t base = smem_u32(dsm);

    const int tid  = threadIdx.x;
    const int wid  = tid >> 5;
    const int lane = tid & 31;
    const int bm = blockIdx.y * 128;
    const int bn = blockIdx.x * 128;
    const int wm = (wid & 3) * 32;     // warp M offset
    const int wn = (wid >> 2) * 64;    // warp N offset

    const __half* srcs[4] = {
        Ahi + (size_t)bm * CH, Alo + (size_t)bm * CH,
        Bhi + (size_t)bn * CH, Blo + (size_t)bn * CH };

    auto load_stage = [&](int st, int kc) {
        const uint32_t sb = base + st * HSTAGE;
#pragma unroll
        for (int p = 0; p < 8; p++) {
            int idx = p * 256 + tid;       // 0..2047
            int buf = idx >> 9;            // 0..3
            int rem = idx & 511;
            int row = rem >> 2;            // 0..127
            int ch  = rem & 3;             // 16B chunk
            const __half* s = srcs[buf] + (size_t)row * CH + kc * BKH + ch * 8;
            cp16(sb + buf * HT_BYTES + sw_off(row, ch), s);
        }
        cp_commit();
    };

    float acc[2][8][4];
#pragma unroll
    for (int mi = 0; mi < 2; mi++)
#pragma unroll
        for (int ni = 0; ni < 8; ni++)
#pragma unroll
            for (int t = 0; t < 4; t++) acc[mi][ni][t] = 0.0f;

    load_stage(0, 0);
    load_stage(1, 1);

    const int lr = lane & 15;      // ldmatrix row-in-group
    const int lc = lane >> 4;      // ldmatrix k8-chunk select

    for (int kc = 0; kc < NKC; kc++) {
        if (kc < NKC - 1) cp_wait<1>(); else cp_wait<0>();
        __syncthreads();

        const uint32_t sb = base + (kc % 3) * HSTAGE;
        const uint32_t aHib = sb;
        const uint32_t aLob = sb + HT_BYTES;
        const uint32_t bHib = sb + 2 * HT_BYTES;
        const uint32_t bLob = sb + 3 * HT_BYTES;

#pragma unroll
        for (int ks = 0; ks < 2; ks++) {
            const int chnk = ks * 2 + lc;
            uint32_t ah[2][4], al[2][4], bh[4][4], bl[4][4];
#pragma unroll
            for (int mi = 0; mi < 2; mi++) {
                uint32_t off = sw_off(wm + mi * 16 + lr, chnk);
                ldsm4(ah[mi][0], ah[mi][1], ah[mi][2], ah[mi][3], aHib + off);
                ldsm4(al[mi][0], al[mi][1], al[mi][2], al[mi][3], aLob + off);
            }
#pragma unroll
            for (int g = 0; g < 4; g++) {
                uint32_t off = sw_off(wn + g * 16 + lr, chnk);
                ldsm4(bh[g][0], bh[g][1], bh[g][2], bh[g][3], bHib + off);
                ldsm4(bl[g][0], bl[g][1], bl[g][2], bl[g][3], bLob + off);
            }
            // n8 fragment ni: group g = ni>>1, regs {r[ni&1], r[(ni&1)+2]}
#pragma unroll
            for (int mi = 0; mi < 2; mi++)
#pragma unroll
                for (int ni = 0; ni < 8; ni++) {
                    const int g = ni >> 1, w = ni & 1;
                    mma16816(acc[mi][ni], ah[mi], bh[g][w], bh[g][w + 2]); // hi*hi
                    mma16816(acc[mi][ni], ah[mi], bl[g][w], bl[g][w + 2]); // hi*lo
                    mma16816(acc[mi][ni], al[mi], bh[g][w], bh[g][w + 2]); // lo*hi
                }
        }
        __syncthreads();
        if (kc + 2 < NKC) load_stage((kc + 2) % 3, kc + 2);
    }

    // epilogue: C frag m16n8 -> rows (lane>>2, +8), cols 2*(lane&3)+{0,1}
#pragma unroll
    for (int mi = 0; mi < 2; mi++) {
        const int r0 = bm + wm + mi * 16 + (lane >> 2);
#pragma unroll
        for (int ni = 0; ni < 8; ni++) {
            const int c = bn + wn + ni * 8 + (lane & 3) * 2;
            const float b0 = bias[c], b1 = bias[c + 1];
            float2 v0 = make_float2(acc[mi][ni][0] + b0, acc[mi][ni][1] + b1);
            float2 v1 = make_float2(acc[mi][ni][2] + b0, acc[mi][ni][3] + b1);
            *(float2*)(Out + (size_t)r0 * CH + c)       = v0;
            *(float2*)(Out + (size_t)(r0 + 8) * CH + c) = v1;
        }
    }
}

// ---------------- attention: one CTA per (block n, head h, batch b) --------
#define QT_STRIDE 68
#define KT_STRIDE 196
#define SS_STRIDE 196
#define VS_STRIDE 68
#define QT_OFF 0
#define KV_OFF (64 * QT_STRIDE)
#define KV_FLOATS 13056
#define SS_OFF (KV_OFF + KV_FLOATS)
#define SMEM_FLOATS (SS_OFF + 64 * SS_STRIDE)
#define ATTN_SMEM_BYTES (SMEM_FLOATS * 4)

__global__ __launch_bounds__(256) void attn_kernel(
    const float* __restrict__ Q, const float* __restrict__ K,
    const float* __restrict__ V, float* __restrict__ O)
{
    extern __shared__ float sm[];
    float* qT = sm + QT_OFF;
    float* kT = sm + KV_OFF;
    float* vs = sm + KV_OFF;
    float* Ss = sm + SS_OFF;

    const int tid = threadIdx.x;
    const int n = blockIdx.x;
    const int h = blockIdx.y;
    const int b = blockIdx.z;
    const size_t base = (size_t)b * SEQ * CH + (size_t)h * HD;

#pragma unroll
    for (int p = 0; p < 4; p++) {
        int idx = tid + p * 256;
        int i   = idx >> 4;
        int dd0 = (idx & 15) << 2;
        float4 v4 = *(const float4*)(Q + base + (size_t)(n * BS + i) * CH + dd0);
        qT[(dd0 + 0) * QT_STRIDE + i] = v4.x;
        qT[(dd0 + 1) * QT_STRIDE + i] = v4.y;
        qT[(dd0 + 2) * QT_STRIDE + i] = v4.z;
        qT[(dd0 + 3) * QT_STRIDE + i] = v4.w;
    }
#pragma unroll
    for (int p = 0; p < 12; p++) {
        int idx = tid + p * 256;
        int j   = idx >> 4;
        int dd0 = (idx & 15) << 2;
        int kpos = (n - 1) * BS + j;
        float4 v4 = make_float4(0.f, 0.f, 0.f, 0.f);
        if (kpos >= 0 && kpos < SEQ)
            v4 = *(const float4*)(K + base + (size_t)kpos * CH + dd0);
        kT[(dd0 + 0) * KT_STRIDE + j] = v4.x;
        kT[(dd0 + 1) * KT_STRIDE + j] = v4.y;
        kT[(dd0 + 2) * KT_STRIDE + j] = v4.z;
        kT[(dd0 + 3) * KT_STRIDE + j] = v4.w;
    }
    __syncthreads();

    const int i0 = (tid >> 4) << 2;
    const int j0 = (tid & 15) * 12;
    float acc[4][12];
#pragma unroll
    for (int ii = 0; ii < 4; ii++)
#pragma unroll
        for (int jj = 0; jj < 12; jj++) acc[ii][jj] = 0.0f;

#pragma unroll 4
    for (int dd = 0; dd < 64; dd++) {
        float4 a4 = *(const float4*)&qT[dd * QT_STRIDE + i0];
        float4 b0 = *(const float4*)&kT[dd * KT_STRIDE + j0];
        float4 b1 = *(const float4*)&kT[dd * KT_STRIDE + j0 + 4];
        float4 b2 = *(const float4*)&kT[dd * KT_STRIDE + j0 + 8];
        float a[4] = {a4.x, a4.y, a4.z, a4.w};
        float bb[12] = {b0.x, b0.y, b0.z, b0.w, b1.x, b1.y, b1.z, b1.w,
                        b2.x, b2.y, b2.z, b2.w};
#pragma unroll
        for (int ii = 0; ii < 4; ii++)
#pragma unroll
            for (int jj = 0; jj < 12; jj++)
                acc[ii][jj] += a[ii] * bb[jj];
    }

    const float scale = 0.125f;
#pragma unroll
    for (int ii = 0; ii < 4; ii++) {
        int i = i0 + ii;
#pragma unroll
        for (int jj = 0; jj < 12; jj++) {
            int j = j0 + jj;
            bool valid = (j <= i + BS) &&
                         (n > 0 || j >= BS) &&
                         (n < NB - 1 || j < 2 * BS);
            Ss[i * SS_STRIDE + j] = valid ? acc[ii][jj] * scale : -1e30f;
        }
    }
    __syncthreads();

    {
        int r  = tid >> 2;
        int jc = tid & 3;
        float vals[48];
        float m = -1e30f;
#pragma unroll
        for (int t = 0; t < 48; t++) {
            vals[t] = Ss[r * SS_STRIDE + jc + 4 * t];
            m = fmaxf(m, vals[t]);
        }
        m = fmaxf(m, __shfl_xor_sync(0xffffffffu, m, 1));
        m = fmaxf(m, __shfl_xor_sync(0xffffffffu, m, 2));
        float s = 0.0f;
#pragma unroll
        for (int t = 0; t < 48; t++) {
            vals[t] = __expf(vals[t] - m);
            s += vals[t];
        }
        s += __shfl_xor_sync(0xffffffffu, s, 1);
        s += __shfl_xor_sync(0xffffffffu, s, 2);
        float inv = 1.0f / s;
#pragma unroll
        for (int t = 0; t < 48; t++)
            Ss[r * SS_STRIDE + jc + 4 * t] = vals[t] * inv;
    }

#pragma unroll
    for (int p = 0; p < 12; p++) {
        int idx = tid + p * 256;
        int j   = idx >> 4;
        int dd0 = (idx & 15) << 2;
        int kpos = (n - 1) * BS + j;
        float4 v4 = make_float4(0.f, 0.f, 0.f, 0.f);
        if (kpos >= 0 && kpos < SEQ)
            v4 = *(const float4*)(V + base + (size_t)kpos * CH + dd0);
        *(float4*)&vs[j * VS_STRIDE + dd0] = v4;
    }
    __syncthreads();

    const int c0 = (tid & 15) << 2;
    float o[4][4];
#pragma unroll
    for (int ii = 0; ii < 4; ii++)
#pragma unroll
        for (int cc = 0; cc < 4; cc++) o[ii][cc] = 0.0f;

#pragma unroll 4
    for (int j = 0; j < 192; j++) {
        float4 v4 = *(const float4*)&vs[j * VS_STRIDE + c0];
        float p0 = Ss[(i0 + 0) * SS_STRIDE + j];
        float p1 = Ss[(i0 + 1) * SS_STRIDE + j];
        float p2 = Ss[(i0 + 2) * SS_STRIDE + j];
        float p3 = Ss[(i0 + 3) * SS_STRIDE + j];
        o[0][0] += p0 * v4.x; o[0][1] += p0 * v4.y; o[0][2] += p0 * v4.z; o[0][3] += p0 * v4.w;
        o[1][0] += p1 * v4.x; o[1][1] += p1 * v4.y; o[1][2] += p1 * v4.z; o[1][3] += p1 * v4.w;
        o[2][0] += p2 * v4.x; o[2][1] += p2 * v4.y; o[2][2] += p2 * v4.z; o[2][3] += p2 * v4.w;
        o[3][0] += p3 * v4.x; o[3][1] += p3 * v4.y; o[3][2] += p3 * v4.z; o[3][3] += p3 * v4.w;
    }
#pragma unroll
    for (int ii = 0; ii < 4; ii++) {
        float4 w4 = make_float4(o[ii][0], o[ii][1], o[ii][2], o[ii][3]);
        *(float4*)(O + base + (size_t)(n * BS + i0 + ii) * CH + c0) = w4;
    }
}

// ---------------------------------------------------------------------------
extern "C" void kernel_launch(void* const* d_in, const int* in_sizes, int n_in,
                              void* d_out, int out_size)
{
    const float* x  = (const float*)d_in[0];
    const float* Wq = (const float*)d_in[1];
    const float* bq = (const float*)d_in[2];
    const float* Wk = (const float*)d_in[3];
    const float* bk = (const float*)d_in[4];
    const float* Wv = (const float*)d_in[5];
    const float* bv = (const float*)d_in[6];
    const float* Wo = (const float*)d_in[7];
    const float* bo = (const float*)d_in[8];
    float* out = (float*)d_out;

    float *qp, *kp, *vp, *op;
    __half *ahi, *alo, *phi, *plo, *whi, *wlo;
    cudaGetSymbolAddress((void**)&qp,  g_Q);
    cudaGetSymbolAddress((void**)&kp,  g_K);
    cudaGetSymbolAddress((void**)&vp,  g_V);
    cudaGetSymbolAddress((void**)&op,  g_O);
    cudaGetSymbolAddress((void**)&ahi, g_Ahi);
    cudaGetSymbolAddress((void**)&alo, g_Alo);
    cudaGetSymbolAddress((void**)&phi, g_Phi);
    cudaGetSymbolAddress((void**)&plo, g_Plo);
    cudaGetSymbolAddress((void**)&whi, g_Whi);
    cudaGetSymbolAddress((void**)&wlo, g_Wlo);

    cudaFuncSetAttribute(attn_kernel,
                         cudaFuncAttributeMaxDynamicSharedMemorySize, ATTN_SMEM_BYTES);
    cudaFuncSetAttribute(gemm_hmma,
                         cudaFuncAttributeMaxDynamicSharedMemorySize, HGEMM_SMEM);

    const int NX = MROWS * CH;   // 16.7M
    const int NW = CH * CH;      // 1M

    split_f16<<<NX / 1024, 256>>>(x,  ahi, alo, NX);
    split_f16<<<NW / 1024, 256>>>(Wq, whi + 0 * (size_t)NW, wlo + 0 * (size_t)NW, NW);
    split_f16<<<NW / 1024, 256>>>(Wk, whi + 1 * (size_t)NW, wlo + 1 * (size_t)NW, NW);
    split_f16<<<NW / 1024, 256>>>(Wv, whi + 2 * (size_t)NW, wlo + 2 * (size_t)NW, NW);
    split_f16<<<NW / 1024, 256>>>(Wo, whi + 3 * (size_t)NW, wlo + 3 * (size_t)NW, NW);

    dim3 ggrid(CH / 128, MROWS / 128);   // (8, 128)
    gemm_hmma<<<ggrid, 256, HGEMM_SMEM>>>(ahi, alo, whi + 0 * (size_t)NW, wlo + 0 * (size_t)NW, bq, qp);
    gemm_hmma<<<ggrid, 256, HGEMM_SMEM>>>(ahi, alo, whi + 1 * (size_t)NW, wlo + 1 * (size_t)NW, bk, kp);
    gemm_hmma<<<ggrid, 256, HGEMM_SMEM>>>(ahi, alo, whi + 2 * (size_t)NW, wlo + 2 * (size_t)NW, bv, vp);

    attn_kernel<<<dim3(NB, NH, BATCH), 256, ATTN_SMEM_BYTES>>>(qp, kp, vp, op);

    split_f16<<<NX / 1024, 256>>>(op, phi, plo, NX);
    gemm_hmma<<<ggrid, 256, HGEMM_SMEM>>>(phi, plo, whi + 3 * (size_t)NW, wlo + 3 * (size_t)NW, bo, out);
}

// round 4
// speedup vs baseline: 2.9335x; 1.4190x over previous
#include <cuda_runtime.h>
#include <cuda_fp16.h>
#include <cstdint>

#define BATCH 4
#define SEQ   4096
#define CH    1024
#define NH    16
#define HD    64
#define BS    64
#define NB    (SEQ / BS)          // 64
#define MROWS (BATCH * SEQ)       // 16384

// ---------------- scratch (device globals: allocation-free) ----------------
__device__ float g_Q[(size_t)MROWS * CH];
__device__ float g_K[(size_t)MROWS * CH];
__device__ float g_V[(size_t)MROWS * CH];
__device__ __half g_Ahi[(size_t)MROWS * CH];
__device__ __half g_Alo[(size_t)MROWS * CH];
__device__ __half g_Phi[(size_t)MROWS * CH];
__device__ __half g_Plo[(size_t)MROWS * CH];
__device__ __half g_Whi[(size_t)4 * CH * CH];

// =================== helpers ===================
__device__ __forceinline__ uint32_t smem_u32(const void* p) {
    uint32_t a;
    asm("{ .reg .u64 t; cvta.to.shared.u64 t, %1; cvt.u32.u64 %0, t; }"
        : "=r"(a) : "l"(p));
    return a;
}
__device__ __forceinline__ void cp16(uint32_t dst, const void* src) {
    asm volatile("cp.async.cg.shared.global [%0], [%1], 16;" :: "r"(dst), "l"(src));
}
__device__ __forceinline__ void cp_commit() {
    asm volatile("cp.async.commit_group;" ::: "memory");
}
template <int N>
__device__ __forceinline__ void cp_wait() {
    asm volatile("cp.async.wait_group %0;" :: "n"(N) : "memory");
}
__device__ __forceinline__ void ldsm4(uint32_t& r0, uint32_t& r1, uint32_t& r2,
                                      uint32_t& r3, uint32_t addr) {
    asm volatile("ldmatrix.sync.aligned.m8n8.x4.shared.b16 {%0,%1,%2,%3}, [%4];"
                 : "=r"(r0), "=r"(r1), "=r"(r2), "=r"(r3) : "r"(addr));
}
__device__ __forceinline__ void mma16816(float* c, const uint32_t* a,
                                         uint32_t b0, uint32_t b1) {
    asm volatile(
        "mma.sync.aligned.m16n8k16.row.col.f32.f16.f16.f32 "
        "{%0,%1,%2,%3}, {%4,%5,%6,%7}, {%8,%9}, {%0,%1,%2,%3};"
        : "+f"(c[0]), "+f"(c[1]), "+f"(c[2]), "+f"(c[3])
        : "r"(a[0]), "r"(a[1]), "r"(a[2]), "r"(a[3]), "r"(b0), "r"(b1));
}

// =================== fp32 -> fp16 hi/lo splitter ===================
__global__ __launch_bounds__(256) void split_f16(
    const float* __restrict__ in, __half* __restrict__ hi,
    __half* __restrict__ lo, int n)
{
    int i = (blockIdx.x * 256 + threadIdx.x) * 4;
    if (i >= n) return;
    float4 v = *(const float4*)(in + i);
    __half h0 = __float2half(v.x);
    __half h1 = __float2half(v.y);
    __half h2 = __float2half(v.z);
    __half h3 = __float2half(v.w);
    __half2 hp0; hp0.x = h0; hp0.y = h1;
    __half2 hp1; hp1.x = h2; hp1.y = h3;
    __half2 lp0; lp0.x = __float2half(v.x - __half2float(h0));
    lp0.y = __float2half(v.y - __half2float(h1));
    __half2 lp1; lp1.x = __float2half(v.z - __half2float(h2));
    lp1.y = __float2half(v.w - __half2float(h3));
    *(__half2*)(hi + i)     = hp0;
    *(__half2*)(hi + i + 2) = hp1;
    *(__half2*)(lo + i)     = lp0;
    *(__half2*)(lo + i + 2) = lp1;
}
// weights: hi only
__global__ __launch_bounds__(256) void to_f16(
    const float* __restrict__ in, __half* __restrict__ hi, int n)
{
    int i = (blockIdx.x * 256 + threadIdx.x) * 4;
    if (i >= n) return;
    float4 v = *(const float4*)(in + i);
    __half2 hp0; hp0.x = __float2half(v.x); hp0.y = __float2half(v.y);
    __half2 hp1; hp1.x = __float2half(v.z); hp1.y = __float2half(v.w);
    *(__half2*)(hi + i)     = hp0;
    *(__half2*)(hi + i + 2) = hp1;
}

// =================== HMMA GEMM: Out = A@W^T + bias (A=fp16x2, W=fp16) =======
// BM=BN=128, BK=32 halfs, 3-stage cp.async, 8 warps (32x64 warp tiles).
#define BKH 32
#define NKC (CH / BKH)            // 32
#define HT_BYTES 8192             // 128 rows * 64B
#define HSTAGE (3 * HT_BYTES)     // Ahi, Alo, Bh
#define HGEMM_SMEM (3 * HSTAGE)   // 73728

__device__ __forceinline__ uint32_t sw_off(int row, int chunk) {
    return (uint32_t)(row * 64 + ((chunk ^ ((row >> 1) & 3)) << 4));
}

__global__ __launch_bounds__(256) void gemm_hmma(
    const __half* __restrict__ Ahi, const __half* __restrict__ Alo,
    const __half* __restrict__ Bh,
    const float* __restrict__ bias, float* __restrict__ Out)
{
    extern __shared__ char dsm[];
    const uint32_t base = smem_u32(dsm);

    const int tid  = threadIdx.x;
    const int wid  = tid >> 5;
    const int lane = tid & 31;
    const int bm = blockIdx.y * 128;
    const int bn = blockIdx.x * 128;
    const int wm = (wid & 3) * 32;
    const int wn = (wid >> 2) * 64;

    const __half* srcs[3] = {
        Ahi + (size_t)bm * CH, Alo + (size_t)bm * CH, Bh + (size_t)bn * CH };

    auto load_stage = [&](int st, int kc) {
        const uint32_t sb = base + st * HSTAGE;
#pragma unroll
        for (int p = 0; p < 6; p++) {
            int idx = p * 256 + tid;       // 0..1535
            int buf = idx >> 9;            // 0..2
            int rem = idx & 511;
            int row = rem >> 2;            // 0..127
            int ch  = rem & 3;
            const __half* s = srcs[buf] + (size_t)row * CH + kc * BKH + ch * 8;
            cp16(sb + buf * HT_BYTES + sw_off(row, ch), s);
        }
        cp_commit();
    };

    float acc[2][8][4];
#pragma unroll
    for (int mi = 0; mi < 2; mi++)
#pragma unroll
        for (int ni = 0; ni < 8; ni++)
#pragma unroll
            for (int t = 0; t < 4; t++) acc[mi][ni][t] = 0.0f;

    load_stage(0, 0);
    load_stage(1, 1);

    const int lr = lane & 15;
    const int lc = lane >> 4;

    for (int kc = 0; kc < NKC; kc++) {
        if (kc < NKC - 1) cp_wait<1>(); else cp_wait<0>();
        __syncthreads();

        const uint32_t sb = base + (kc % 3) * HSTAGE;
        const uint32_t aHib = sb;
        const uint32_t aLob = sb + HT_BYTES;
        const uint32_t bHib = sb + 2 * HT_BYTES;

#pragma unroll
        for (int ks = 0; ks < 2; ks++) {
            const int chnk = ks * 2 + lc;
            uint32_t ah[2][4], al[2][4], bh[4][4];
#pragma unroll
            for (int mi = 0; mi < 2; mi++) {
                uint32_t off = sw_off(wm + mi * 16 + lr, chnk);
                ldsm4(ah[mi][0], ah[mi][1], ah[mi][2], ah[mi][3], aHib + off);
                ldsm4(al[mi][0], al[mi][1], al[mi][2], al[mi][3], aLob + off);
            }
#pragma unroll
            for (int g = 0; g < 4; g++) {
                uint32_t off = sw_off(wn + g * 16 + lr, chnk);
                ldsm4(bh[g][0], bh[g][1], bh[g][2], bh[g][3], bHib + off);
            }
#pragma unroll
            for (int mi = 0; mi < 2; mi++)
#pragma unroll
                for (int ni = 0; ni < 8; ni++) {
                    const int g = ni >> 1, w = ni & 1;
                    mma16816(acc[mi][ni], ah[mi], bh[g][w], bh[g][w + 2]);
                    mma16816(acc[mi][ni], al[mi], bh[g][w], bh[g][w + 2]);
                }
        }
        if (kc + 2 < NKC) load_stage((kc + 2) % 3, kc + 2);
    }

#pragma unroll
    for (int mi = 0; mi < 2; mi++) {
        const int r0 = bm + wm + mi * 16 + (lane >> 2);
#pragma unroll
        for (int ni = 0; ni < 8; ni++) {
            const int c = bn + wn + ni * 8 + (lane & 3) * 2;
            const float b0 = bias[c], b1 = bias[c + 1];
            float2 v0 = make_float2(acc[mi][ni][0] + b0, acc[mi][ni][1] + b1);
            float2 v1 = make_float2(acc[mi][ni][2] + b0, acc[mi][ni][3] + b1);
            *(float2*)(Out + (size_t)r0 * CH + c)       = v0;
            *(float2*)(Out + (size_t)(r0 + 8) * CH + c) = v1;
        }
    }
}

// ---------------- attention: one CTA per (block n, head h, batch b) --------
// smem (floats): qT[64][68]; kv region (kT[64][196] -> vs[192][68]); P fp16 [64][196]
#define QT_STRIDE 68
#define KT_STRIDE 196
#define VS_STRIDE 68
#define PS_STRIDE 196
#define QT_OFF 0
#define KV_OFF (64 * QT_STRIDE)                  // 4352
#define KV_FLOATS 13056
#define PS_OFF (KV_OFF + KV_FLOATS)              // 17408 (floats)
#define SMEM_FLOATS (PS_OFF + (64 * PS_STRIDE + 1) / 2)  // + 6272
#define ATTN_SMEM_BYTES (SMEM_FLOATS * 4)        // 94720

__global__ __launch_bounds__(256, 2) void attn_kernel(
    const float* __restrict__ Q, const float* __restrict__ K,
    const float* __restrict__ V,
    __half* __restrict__ Ohi, __half* __restrict__ Olo)
{
    extern __shared__ float sm[];
    float*  qT  = sm + QT_OFF;
    float*  kT  = sm + KV_OFF;
    float*  vs  = sm + KV_OFF;
    __half* Ps  = (__half*)(sm + PS_OFF);

    const int tid = threadIdx.x;
    const int n = blockIdx.x;
    const int h = blockIdx.y;
    const int b = blockIdx.z;
    const size_t base = (size_t)b * SEQ * CH + (size_t)h * HD;

#pragma unroll
    for (int p = 0; p < 4; p++) {
        int idx = tid + p * 256;
        int i   = idx >> 4;
        int dd0 = (idx & 15) << 2;
        float4 v4 = *(const float4*)(Q + base + (size_t)(n * BS + i) * CH + dd0);
        qT[(dd0 + 0) * QT_STRIDE + i] = v4.x;
        qT[(dd0 + 1) * QT_STRIDE + i] = v4.y;
        qT[(dd0 + 2) * QT_STRIDE + i] = v4.z;
        qT[(dd0 + 3) * QT_STRIDE + i] = v4.w;
    }
#pragma unroll
    for (int p = 0; p < 12; p++) {
        int idx = tid + p * 256;
        int j   = idx >> 4;
        int dd0 = (idx & 15) << 2;
        int kpos = (n - 1) * BS + j;
        float4 v4 = make_float4(0.f, 0.f, 0.f, 0.f);
        if (kpos >= 0 && kpos < SEQ)
            v4 = *(const float4*)(K + base + (size_t)kpos * CH + dd0);
        kT[(dd0 + 0) * KT_STRIDE + j] = v4.x;
        kT[(dd0 + 1) * KT_STRIDE + j] = v4.y;
        kT[(dd0 + 2) * KT_STRIDE + j] = v4.z;
        kT[(dd0 + 3) * KT_STRIDE + j] = v4.w;
    }
    __syncthreads();

    const int i0 = (tid >> 4) << 2;      // 4 rows per 16-thread group
    const int j0 = (tid & 15) * 12;      // 12 cols per thread
    float acc[4][12];
#pragma unroll
    for (int ii = 0; ii < 4; ii++)
#pragma unroll
        for (int jj = 0; jj < 12; jj++) acc[ii][jj] = 0.0f;

#pragma unroll 4
    for (int dd = 0; dd < 64; dd++) {
        float4 a4 = *(const float4*)&qT[dd * QT_STRIDE + i0];
        float4 b0 = *(const float4*)&kT[dd * KT_STRIDE + j0];
        float4 b1 = *(const float4*)&kT[dd * KT_STRIDE + j0 + 4];
        float4 b2 = *(const float4*)&kT[dd * KT_STRIDE + j0 + 8];
        float a[4] = {a4.x, a4.y, a4.z, a4.w};
        float bb[12] = {b0.x, b0.y, b0.z, b0.w, b1.x, b1.y, b1.z, b1.w,
                        b2.x, b2.y, b2.z, b2.w};
#pragma unroll
        for (int ii = 0; ii < 4; ii++)
#pragma unroll
            for (int jj = 0; jj < 12; jj++)
                acc[ii][jj] += a[ii] * bb[jj];
    }

    // mask + scale in registers
    const float scale = 0.125f;
    float mrow[4] = {-1e30f, -1e30f, -1e30f, -1e30f};
#pragma unroll
    for (int ii = 0; ii < 4; ii++) {
        const int i = i0 + ii;
#pragma unroll
        for (int jj = 0; jj < 12; jj++) {
            const int j = j0 + jj;
            bool valid = (j <= i + BS) &&
                         (n > 0 || j >= BS) &&
                         (n < NB - 1 || j < 2 * BS);
            acc[ii][jj] = valid ? acc[ii][jj] * scale : -1e30f;
            mrow[ii] = fmaxf(mrow[ii], acc[ii][jj]);
        }
    }
    // reduce across the 16-thread row group (xor < 16 stays in-group)
#pragma unroll
    for (int ii = 0; ii < 4; ii++) {
        mrow[ii] = fmaxf(mrow[ii], __shfl_xor_sync(0xffffffffu, mrow[ii], 1));
        mrow[ii] = fmaxf(mrow[ii], __shfl_xor_sync(0xffffffffu, mrow[ii], 2));
        mrow[ii] = fmaxf(mrow[ii], __shfl_xor_sync(0xffffffffu, mrow[ii], 4));
        mrow[ii] = fmaxf(mrow[ii], __shfl_xor_sync(0xffffffffu, mrow[ii], 8));
    }
    float srow[4] = {0.f, 0.f, 0.f, 0.f};
#pragma unroll
    for (int ii = 0; ii < 4; ii++)
#pragma unroll
        for (int jj = 0; jj < 12; jj++) {
            acc[ii][jj] = __expf(acc[ii][jj] - mrow[ii]);
            srow[ii] += acc[ii][jj];
        }
#pragma unroll
    for (int ii = 0; ii < 4; ii++) {
        srow[ii] += __shfl_xor_sync(0xffffffffu, srow[ii], 1);
        srow[ii] += __shfl_xor_sync(0xffffffffu, srow[ii], 2);
        srow[ii] += __shfl_xor_sync(0xffffffffu, srow[ii], 4);
        srow[ii] += __shfl_xor_sync(0xffffffffu, srow[ii], 8);
        const float inv = 1.0f / srow[ii];
#pragma unroll
        for (int jj = 0; jj < 12; jj++)
            Ps[(i0 + ii) * PS_STRIDE + j0 + jj] = __float2half(acc[ii][jj] * inv);
    }
    __syncthreads();   // all kT reads done; Ps visible

    // load v over kT region
#pragma unroll
    for (int p = 0; p < 12; p++) {
        int idx = tid + p * 256;
        int j   = idx >> 4;
        int dd0 = (idx & 15) << 2;
        int kpos = (n - 1) * BS + j;
        float4 v4 = make_float4(0.f, 0.f, 0.f, 0.f);
        if (kpos >= 0 && kpos < SEQ)
            v4 = *(const float4*)(V + base + (size_t)kpos * CH + dd0);
        *(float4*)&vs[j * VS_STRIDE + dd0] = v4;
    }
    __syncthreads();

    const int c0 = (tid & 15) << 2;
    float o[4][4];
#pragma unroll
    for (int ii = 0; ii < 4; ii++)
#pragma unroll
        for (int cc = 0; cc < 4; cc++) o[ii][cc] = 0.0f;

#pragma unroll 4
    for (int j = 0; j < 192; j++) {
        float4 v4 = *(const float4*)&vs[j * VS_STRIDE + c0];
        float p0 = __half2float(Ps[(i0 + 0) * PS_STRIDE + j]);
        float p1 = __half2float(Ps[(i0 + 1) * PS_STRIDE + j]);
        float p2 = __half2float(Ps[(i0 + 2) * PS_STRIDE + j]);
        float p3 = __half2float(Ps[(i0 + 3) * PS_STRIDE + j]);
        o[0][0] += p0 * v4.x; o[0][1] += p0 * v4.y; o[0][2] += p0 * v4.z; o[0][3] += p0 * v4.w;
        o[1][0] += p1 * v4.x; o[1][1] += p1 * v4.y; o[1][2] += p1 * v4.z; o[1][3] += p1 * v4.w;
        o[2][0] += p2 * v4.x; o[2][1] += p2 * v4.y; o[2][2] += p2 * v4.z; o[2][3] += p2 * v4.w;
        o[3][0] += p3 * v4.x; o[3][1] += p3 * v4.y; o[3][2] += p3 * v4.z; o[3][3] += p3 * v4.w;
    }
    // write fp16 hi/lo directly (feeds the output GEMM)
#pragma unroll
    for (int ii = 0; ii < 4; ii++) {
        const size_t oidx = base + (size_t)(n * BS + i0 + ii) * CH + c0;
        __half h0 = __float2half(o[ii][0]);
        __half h1 = __float2half(o[ii][1]);
        __half h2 = __float2half(o[ii][2]);
        __half h3 = __float2half(o[ii][3]);
        __half2 hp0; hp0.x = h0; hp0.y = h1;
        __half2 hp1; hp1.x = h2; hp1.y = h3;
        __half2 lp0, lp1;
        lp0.x = __float2half(o[ii][0] - __half2float(h0));
        lp0.y = __float2half(o[ii][1] - __half2float(h1));
        lp1.x = __float2half(o[ii][2] - __half2float(h2));
        lp1.y = __float2half(o[ii][3] - __half2float(h3));
        *(__half2*)(Ohi + oidx)     = hp0;
        *(__half2*)(Ohi + oidx + 2) = hp1;
        *(__half2*)(Olo + oidx)     = lp0;
        *(__half2*)(Olo + oidx + 2) = lp1;
    }
}

// ---------------------------------------------------------------------------
extern "C" void kernel_launch(void* const* d_in, const int* in_sizes, int n_in,
                              void* d_out, int out_size)
{
    const float* x  = (const float*)d_in[0];
    const float* Wq = (const float*)d_in[1];
    const float* bq = (const float*)d_in[2];
    const float* Wk = (const float*)d_in[3];
    const float* bk = (const float*)d_in[4];
    const float* Wv = (const float*)d_in[5];
    const float* bv = (const float*)d_in[6];
    const float* Wo = (const float*)d_in[7];
    const float* bo = (const float*)d_in[8];
    float* out = (float*)d_out;

    float *qp, *kp, *vp;
    __half *ahi, *alo, *phi, *plo, *whi;
    cudaGetSymbolAddress((void**)&qp,  g_Q);
    cudaGetSymbolAddress((void**)&kp,  g_K);
    cudaGetSymbolAddress((void**)&vp,  g_V);
    cudaGetSymbolAddress((void**)&ahi, g_Ahi);
    cudaGetSymbolAddress((void**)&alo, g_Alo);
    cudaGetSymbolAddress((void**)&phi, g_Phi);
    cudaGetSymbolAddress((void**)&plo, g_Plo);
    cudaGetSymbolAddress((void**)&whi, g_Whi);

    cudaFuncSetAttribute(attn_kernel,
                         cudaFuncAttributeMaxDynamicSharedMemorySize, ATTN_SMEM_BYTES);
    cudaFuncSetAttribute(gemm_hmma,
                         cudaFuncAttributeMaxDynamicSharedMemorySize, HGEMM_SMEM);

    const int NX = MROWS * CH;   // 16.7M
    const int NW = CH * CH;      // 1M

    split_f16<<<NX / 1024, 256>>>(x, ahi, alo, NX);
    to_f16<<<NW / 1024, 256>>>(Wq, whi + 0 * (size_t)NW, NW);
    to_f16<<<NW / 1024, 256>>>(Wk, whi + 1 * (size_t)NW, NW);
    to_f16<<<NW / 1024, 256>>>(Wv, whi + 2 * (size_t)NW, NW);
    to_f16<<<NW / 1024, 256>>>(Wo, whi + 3 * (size_t)NW, NW);

    dim3 ggrid(CH / 128, MROWS / 128);   // (8, 128)
    gemm_hmma<<<ggrid, 256, HGEMM_SMEM>>>(ahi, alo, whi + 0 * (size_t)NW, bq, qp);
    gemm_hmma<<<ggrid, 256, HGEMM_SMEM>>>(ahi, alo, whi + 1 * (size_t)NW, bk, kp);
    gemm_hmma<<<ggrid, 256, HGEMM_SMEM>>>(ahi, alo, whi + 2 * (size_t)NW, bv, vp);

    attn_kernel<<<dim3(NB, NH, BATCH), 256, ATTN_SMEM_BYTES>>>(qp, kp, vp, phi, plo);

    gemm_hmma<<<ggrid, 256, HGEMM_SMEM>>>(phi, plo, whi + 3 * (size_t)NW, bo, out);
}